// round 14
// baseline (speedup 1.0000x reference)
#include <cuda_runtime.h>
#include <cuda_fp16.h>
#include <cstdint>

// ---------------------------------------------------------------------------
// HydraAttention_v2 — fully tensorized (mma.sync fp16 m16n8k16), fp16 packed
// fragment-layout intermediates. qkv: 4-chunk persistent blocks. conv: warp-
// per-row tiles (64px x 32out), 10-row prestage, paired-B LDS.128, occ 1.
// Launches: prep x3 (0-2), qkv(3=profiled), red, fin, attn, conv x2.
// B=8, C=64, H=W=256, N=65536
// ---------------------------------------------------------------------------

#define BATCH 8
#define CH    64
#define NPIX  65536

typedef unsigned long long ull;

__device__ uint32_t g_QnP[BATCH * NPIX * 32];    // packed fp16 Qn
__device__ uint32_t g_attnP[BATCH * NPIX * 32];  // packed fp16 attn
__device__ uint32_t g_t1P[BATCH * NPIX * 32];    // conv1 out; BEFORE conv1: qkv aggkv scratch
__device__ float    g_ksum[BATCH * CH];
__device__ float    g_vsum[BATCH * CH];
__device__ float    g_aggkv[BATCH * CH * CH];
__device__ float    g_wrvs[BATCH * CH];
__device__ uint32_t g_M2h[BATCH * 2048];         // packed fp16 M2 B-frags
__device__ uint32_t g_qkvB[6144];                // packed fp16 QKV weights
__device__ uint32_t g_convB[2 * 36 * 512];       // packed fp16 conv weights (paired-nf)

// ---- helpers ----------------------------------------------------------------
__device__ __forceinline__ void mma_fp16(float c[4], uint32_t a0, uint32_t a1,
                                         uint32_t a2, uint32_t a3,
                                         uint32_t b0, uint32_t b1) {
    asm volatile(
        "mma.sync.aligned.m16n8k16.row.col.f32.f16.f16.f32 "
        "{%0,%1,%2,%3}, {%4,%5,%6,%7}, {%8,%9}, {%0,%1,%2,%3};"
        : "+f"(c[0]), "+f"(c[1]), "+f"(c[2]), "+f"(c[3])
        : "r"(a0), "r"(a1), "r"(a2), "r"(a3), "r"(b0), "r"(b1));
}
__device__ __forceinline__ uint32_t h2pack(float a, float b) {
    __half2 h = __float22half2_rn(make_float2(a, b));
    return *(uint32_t*)&h;
}
__device__ __forceinline__ float2 h2up(uint32_t w) {
    __half2 h = *(__half2*)&w;
    return __half22float2(h);
}
__device__ __forceinline__ uint32_t smem_u32(const void* p) {
    uint32_t a;
    asm("{ .reg .u64 t; cvta.to.shared.u64 t, %1; cvt.u32.u64 %0, t; }" : "=r"(a) : "l"(p));
    return a;
}
__device__ __forceinline__ void cp16(uint32_t dst, const void* src, int sz) {
    asm volatile("cp.async.ca.shared.global [%0], [%1], 16, %2;"
                 :: "r"(dst), "l"(src), "r"(sz) : "memory");
}
#define CP_COMMIT() asm volatile("cp.async.commit_group;" ::: "memory")
#define CP_WAIT0()  asm volatile("cp.async.wait_group 0;" ::: "memory")

// ---------------------------------------------------------------------------
// prep phases: 0 = conv weights (paired-nf layout), 1 = qkv weights, 2 = zeros
// conv B word f (per conv, per chunk=tap*4+kc, 512 words):
//   w = nfp*128 + (g*4+tig)*4 + j*2 + s ; nf = 2*nfp + j ; n = nf*8+g ;
//   ch = kc*16 + tig*2 + s*8 ; packs (ch, ch+1)
__global__ void k_prep(const float* __restrict__ Wq, const float* __restrict__ Wk,
                       const float* __restrict__ Wv,
                       const float* __restrict__ W1, const float* __restrict__ W2,
                       int phase) {
    int i = blockIdx.x * 256 + threadIdx.x;
    if (phase == 0) {
        if (i >= 36864) return;
        int conv = i / 18432;
        int r    = i % 18432;
        int chunk = r >> 9;
        int w     = r & 511;
        int nfp = w >> 7;
        int lt  = (w >> 2) & 31;
        int j   = (w >> 1) & 1;
        int s   = w & 1;
        int g = lt >> 2, tig = lt & 3;
        int nf = 2 * nfp + j;
        int n  = nf * 8 + g;
        int tap = chunk >> 2, kc = chunk & 3;
        int ch = kc * 16 + tig * 2 + s * 8;
        const float* W = conv ? W2 : W1;
        g_convB[i] = h2pack(W[n * 576 + ch * 9 + tap], W[n * 576 + (ch + 1) * 9 + tap]);
    } else if (phase == 1) {
        if (i >= 6144) return;
        int s = i & 1, tig = (i >> 1) & 3, g = (i >> 3) & 7;
        int nf = (i >> 6) % 24, kc = i / (64 * 24);
        int n = nf * 8 + g;
        int ch = kc * 16 + tig * 2 + s * 8;
        const float* W; int row;
        if (n < 64)       { W = Wq; row = n; }
        else if (n < 96)  { W = Wv; row = n - 64; }
        else if (n < 160) { W = Wk; row = n - 96; }
        else              { W = Wv; row = n - 128; }
        g_qkvB[i] = h2pack(W[row * 64 + ch], W[row * 64 + ch + 1]);
    } else {
        if (i < 512) { g_ksum[i] = 0.f; g_vsum[i] = 0.f; }
    }
}

// ---------------------------------------------------------------------------
// k_qkv: 1024 blocks, each processes 4 chunks of 128 px. (unchanged from R13)
#define QK_XA   0
#define QK_B    20480
#define QK_KN   45056
#define QK_V    62464
#define QK_QN   79872
#define QK_SMEM 96768

__global__ void __launch_bounds__(256, 2)
k_qkv(const float* __restrict__ x, const float* __restrict__ bq,
      const float* __restrict__ bk, const float* __restrict__ bv,
      float* __restrict__ gpart) {
    extern __shared__ char sm[];
    uint32_t* Bw  = (uint32_t*)(sm + QK_B);
    __half*   knh = (__half*)(sm + QK_KN);
    __half*   vh  = (__half*)(sm + QK_V);
    uint32_t* qn  = (uint32_t*)(sm + QK_QN);

    const int tid = threadIdx.x;
    const int b   = blockIdx.x >> 7;
    const int seg = blockIdx.x & 127;

    for (int i = tid; i < 6144; i += 256) Bw[i] = g_qkvB[i];

    const int wid = tid >> 5, lane = tid & 31;
    const int g = lane >> 2, tig = lane & 3;
    const int pxq = wid & 3, nh = wid >> 2;
    const int px0 = pxq << 5;
    const int mt = wid & 3, nh2 = wid >> 2;

    float ag[4][4];
#pragma unroll
    for (int nf = 0; nf < 4; nf++)
#pragma unroll
        for (int r = 0; r < 4; r++) ag[nf][r] = 0.f;
    float ksacc = 0.f;

#pragma unroll 1
    for (int c = 0; c < 4; c++) {
        const int n0 = ((seg << 2) + c) << 7;

        {
            const float* xb = x + ((size_t)b << 22) + n0;
            uint32_t* xa = (uint32_t*)(sm + QK_XA);
            for (int i = tid; i < 4096; i += 256) {
                int px = i & 127, p = i >> 7;
                float f0 = __ldg(xb + ((size_t)(2 * p) << 16) + px);
                float f1 = __ldg(xb + ((size_t)(2 * p + 1) << 16) + px);
                int kc = p >> 3, t3 = p & 7;
                int w = kc * 8 + (t3 & 3) * 2 + (t3 >> 2);
                xa[px * 40 + w] = h2pack(f0, f1);
            }
        }
        __syncthreads();

#pragma unroll 1
        for (int mf = 0; mf < 2; mf++) {
            float acc[12][4];
#pragma unroll
            for (int nf = 0; nf < 12; nf++)
#pragma unroll
                for (int r = 0; r < 4; r++) acc[nf][r] = 0.f;

#pragma unroll
            for (int kc = 0; kc < 4; kc++) {
                const char* ab = sm + QK_XA + ((px0 + mf * 16 + g) * 40 + tig * 2) * 4;
                uint2 A0 = *(const uint2*)(ab + kc * 32);
                uint2 A1 = *(const uint2*)(ab + 8 * 160 + kc * 32);
#pragma unroll
                for (int nf = 0; nf < 12; nf++) {
                    int nfg = nh * 12 + nf;
                    uint2 Bv = *(const uint2*)((const char*)Bw +
                                ((kc * 24 + nfg) * 64 + g * 8 + tig * 2) * 4);
                    mma_fp16(acc[nf], A0.x, A1.x, A0.y, A1.y, Bv.x, Bv.y);
                }
            }

#pragma unroll
            for (int nf = 0; nf < 12; nf++) {
                float2 bb;
                if (nh == 0) bb = (nf < 8) ? *(const float2*)(bq + nf * 8 + tig * 2)
                                           : *(const float2*)(bv + (nf - 8) * 8 + tig * 2);
                else         bb = (nf < 8) ? *(const float2*)(bk + nf * 8 + tig * 2)
                                           : *(const float2*)(bv + 32 + (nf - 8) * 8 + tig * 2);
                acc[nf][0] += bb.x; acc[nf][1] += bb.y;
                acc[nf][2] += bb.x; acc[nf][3] += bb.y;
            }

            float ss0 = 0.f, ss1 = 0.f;
#pragma unroll
            for (int nf = 0; nf < 8; nf++) {
                ss0 += acc[nf][0] * acc[nf][0] + acc[nf][1] * acc[nf][1];
                ss1 += acc[nf][2] * acc[nf][2] + acc[nf][3] * acc[nf][3];
            }
            ss0 += __shfl_xor_sync(0xffffffffu, ss0, 1);
            ss0 += __shfl_xor_sync(0xffffffffu, ss0, 2);
            ss1 += __shfl_xor_sync(0xffffffffu, ss1, 1);
            ss1 += __shfl_xor_sync(0xffffffffu, ss1, 2);
            float inv0 = rsqrtf(ss0), inv1 = rsqrtf(ss1);
            const int pxA = px0 + mf * 16 + g, pxB = pxA + 8;

            if (nh == 0) {
#pragma unroll
                for (int nf = 0; nf < 8; nf++) {
                    int w = (nf >> 1) * 8 + tig * 2 + (nf & 1);
                    qn[pxA * 33 + w] = h2pack(acc[nf][0] * inv0, acc[nf][1] * inv0);
                    qn[pxB * 33 + w] = h2pack(acc[nf][2] * inv1, acc[nf][3] * inv1);
                }
            } else {
#pragma unroll
                for (int nf = 0; nf < 8; nf++) {
                    int m = nf * 8 + tig * 2;
                    knh[m * 136 + pxA]       = __float2half(acc[nf][0] * inv0);
                    knh[(m + 1) * 136 + pxA] = __float2half(acc[nf][1] * inv0);
                    knh[m * 136 + pxB]       = __float2half(acc[nf][2] * inv1);
                    knh[(m + 1) * 136 + pxB] = __float2half(acc[nf][3] * inv1);
                }
            }
#pragma unroll
            for (int nf = 8; nf < 12; nf++) {
                int cc = (nh ? 32 : 0) + (nf - 8) * 8 + tig * 2;
                vh[cc * 136 + pxA]       = __float2half(acc[nf][0]);
                vh[(cc + 1) * 136 + pxA] = __float2half(acc[nf][1]);
                vh[cc * 136 + pxB]       = __float2half(acc[nf][2]);
                vh[(cc + 1) * 136 + pxB] = __float2half(acc[nf][3]);
            }
        }
        __syncthreads();

        {
            uint32_t* gq = g_QnP + (((size_t)b << 16) + n0) * 32;
            for (int j = tid; j < 4096; j += 256)
                gq[j] = qn[(j >> 5) * 33 + (j & 31)];
        }

        if (tid < 128) {
            const uint32_t* rw = (tid < 64)
                ? (const uint32_t*)(sm + QK_KN) + tid * 68
                : (const uint32_t*)(sm + QK_V) + (tid - 64) * 68;
#pragma unroll 8
            for (int j = 0; j < 64; j++) { float2 f = h2up(rw[j]); ksacc += f.x + f.y; }
        }

        {
            const uint32_t* knw = (const uint32_t*)(sm + QK_KN);
            const uint32_t* vw  = (const uint32_t*)(sm + QK_V);
#pragma unroll
            for (int kc = 0; kc < 8; kc++) {
                int ra = (mt * 16 + g) * 68 + kc * 8 + tig;
                uint32_t a0 = knw[ra],          a2 = knw[ra + 4];
                uint32_t a1 = knw[ra + 8 * 68], a3 = knw[ra + 8 * 68 + 4];
#pragma unroll
                for (int nf = 0; nf < 4; nf++) {
                    int rb = (nh2 * 32 + nf * 8 + g) * 68 + kc * 8 + tig;
                    mma_fp16(ag[nf], a0, a1, a2, a3, vw[rb], vw[rb + 4]);
                }
            }
        }
        __syncthreads();
    }

    if (tid < 128) {
        float* dp = (tid < 64) ? &g_ksum[b * 64 + tid] : &g_vsum[b * 64 + tid - 64];
        atomicAdd(dp, ksacc);
    }

    {
        float* agg_s = (float*)(sm + QK_XA);
#pragma unroll
        for (int nf = 0; nf < 4; nf++) {
            int r0 = (mt * 16 + g) * 66 + nh2 * 32 + nf * 8 + tig * 2;
            *(float2*)&agg_s[r0]          = make_float2(ag[nf][0], ag[nf][1]);
            *(float2*)&agg_s[r0 + 8 * 66] = make_float2(ag[nf][2], ag[nf][3]);
        }
        __syncthreads();
        float* gp = gpart + (size_t)blockIdx.x * 4096;
        for (int j = tid; j < 4096; j += 256)
            gp[j] = agg_s[(j >> 6) * 66 + (j & 63)];
    }
}

// ---------------------------------------------------------------------------
__global__ void __launch_bounds__(256, 1)
k_red(const float* __restrict__ gpart) {
    int e = blockIdx.x * 256 + threadIdx.x;
    int b = e >> 12, idx = e & 4095;
    const float* p = gpart + ((size_t)b * 128) * 4096 + idx;
    float s0 = 0.f, s1 = 0.f, s2 = 0.f, s3 = 0.f;
#pragma unroll 4
    for (int q = 0; q < 128; q += 4) {
        s0 += p[(size_t)q * 4096];
        s1 += p[(size_t)(q + 1) * 4096];
        s2 += p[(size_t)(q + 2) * 4096];
        s3 += p[(size_t)(q + 3) * 4096];
    }
    g_aggkv[e] = (s0 + s1) + (s2 + s3);
}

// ---------------------------------------------------------------------------
__global__ void __launch_bounds__(256, 1)
k_fin(const float* __restrict__ Wr) {
    __shared__ float a_s[1024];
    __shared__ float w_s[4096];
    __shared__ float vs_s[64];

    int b  = blockIdx.x >> 2;
    int mq = blockIdx.x & 3;
    int tid = threadIdx.x;

    for (int idx = tid; idx < 4096; idx += 256) {
        int o = idx & 63, c = idx >> 6;
        w_s[c * 64 + o] = Wr[o * 64 + c];
    }
    for (int idx = tid; idx < 1024; idx += 256)
        a_s[idx] = g_aggkv[b * 4096 + mq * 1024 + idx];
    if (tid < 64) vs_s[tid] = g_vsum[b * 64 + tid];
    __syncthreads();

    int o = tid & 63, sub = tid >> 6;
    if (mq == 0 && sub == 0) {
        float s = 0.f;
#pragma unroll 8
        for (int c = 0; c < 64; c++) s += w_s[c * 64 + o] * vs_s[c];
        g_wrvs[b * 64 + o] = s;
    }
    int nf = o >> 3, gg = o & 7;
#pragma unroll
    for (int ml = sub * 4; ml < sub * 4 + 4; ml += 2) {
        int m = mq * 16 + ml;
        float t0 = 0.f, t1 = 0.f;
#pragma unroll 8
        for (int c = 0; c < 64; c++) {
            t0 += w_s[c * 64 + o] * a_s[ml * 64 + c];
            t1 += w_s[c * 64 + o] * a_s[(ml + 1) * 64 + c];
        }
        int kc = m >> 4, r = m & 15;
        int s2 = r >> 3, tg = (r & 7) >> 1;
        g_M2h[b * 2048 + ((kc * 8 + nf) * 64 + gg * 8 + tg * 2 + s2)] = h2pack(t0, t1);
    }
}

// ---------------------------------------------------------------------------
#define AT_QN   0
#define AT_M2   20480
#define AT_KS   28672
#define AT_WV   28928
#define AT_BR   29184
#define AT_SMEM 29440

__global__ void __launch_bounds__(256, 3)
k_attn(const float* __restrict__ br) {
    extern __shared__ char sm[];
    uint32_t* m2  = (uint32_t*)(sm + AT_M2);
    float*    ks  = (float*)(sm + AT_KS);
    float*    wv  = (float*)(sm + AT_WV);
    float*    brs = (float*)(sm + AT_BR);

    const int tid = threadIdx.x;
    const int b  = blockIdx.x >> 9;
    const int n0 = (blockIdx.x & 511) << 7;

    {
        const uint4* gq = (const uint4*)(g_QnP + (((size_t)b << 16) + n0) * 32);
        for (int i = tid; i < 1024; i += 256) {
            int px = i >> 3, q4 = i & 7;
            *(uint4*)(sm + (px * 40 + q4 * 4) * 4) = __ldg(gq + px * 8 + q4);
        }
    }
    for (int i = tid; i < 2048; i += 256) m2[i] = g_M2h[b * 2048 + i];
    if (tid < 64) {
        ks[tid]  = g_ksum[b * 64 + tid] + 1e-6f;
        wv[tid]  = g_wrvs[b * 64 + tid];
        brs[tid] = __ldg(&br[tid]);
    }
    __syncthreads();

    const int wid = tid >> 5, lane = tid & 31;
    const int g = lane >> 2, tig = lane & 3;
    const int px0 = wid << 4;

    float acc[8][4];
#pragma unroll
    for (int nf = 0; nf < 8; nf++)
#pragma unroll
        for (int r = 0; r < 4; r++) acc[nf][r] = 0.f;
    float dot0 = 0.f, dot1 = 0.f;

#pragma unroll
    for (int kc = 0; kc < 4; kc++) {
        const char* ab = sm + ((px0 + g) * 40 + tig * 2) * 4;
        uint2 A0 = *(const uint2*)(ab + kc * 32);
        uint2 A1 = *(const uint2*)(ab + 8 * 160 + kc * 32);
        float2 ka = *(const float2*)&ks[kc * 16 + tig * 2];
        float2 kb = *(const float2*)&ks[kc * 16 + tig * 2 + 8];
        float2 f;
        f = h2up(A0.x); dot0 += f.x * ka.x + f.y * ka.y;
        f = h2up(A0.y); dot0 += f.x * kb.x + f.y * kb.y;
        f = h2up(A1.x); dot1 += f.x * ka.x + f.y * ka.y;
        f = h2up(A1.y); dot1 += f.x * kb.x + f.y * kb.y;
#pragma unroll
        for (int nf = 0; nf < 8; nf++) {
            uint2 Bv = *(const uint2*)((const char*)m2 +
                        ((kc * 8 + nf) * 64 + g * 8 + tig * 2) * 4);
            mma_fp16(acc[nf], A0.x, A1.x, A0.y, A1.y, Bv.x, Bv.y);
        }
    }
    dot0 += __shfl_xor_sync(0xffffffffu, dot0, 1);
    dot0 += __shfl_xor_sync(0xffffffffu, dot0, 2);
    dot1 += __shfl_xor_sync(0xffffffffu, dot1, 1);
    dot1 += __shfl_xor_sync(0xffffffffu, dot1, 2);
    float den0 = 1.f / (65536.f + dot0);
    float den1 = 1.f / (65536.f + dot1);

    uint32_t* ga = g_attnP + (((size_t)b << 16) + n0) * 32;
#pragma unroll
    for (int nf = 0; nf < 8; nf++) {
        int o = nf * 8 + tig * 2;
        int w = (nf >> 1) * 8 + tig * 2 + (nf & 1);
        float v0 = brs[o]     + den0 * (wv[o]     + acc[nf][0]);
        float v1 = brs[o + 1] + den0 * (wv[o + 1] + acc[nf][1]);
        float v2 = brs[o]     + den1 * (wv[o]     + acc[nf][2]);
        float v3 = brs[o + 1] + den1 * (wv[o + 1] + acc[nf][3]);
        ga[(px0 + g) * 32 + w]     = h2pack(v0, v1);
        ga[(px0 + g + 8) * 32 + w] = h2pack(v2, v3);
    }
}

// ---------------------------------------------------------------------------
// conv3x3 via mma.sync fp16: warp = 1 row x 64px x 32out (4 mf x 4 nf).
// Block = 8-row band; 10 rows prestaged via cp.async; single sync; occ 1.
#define CB_OFF   256
#define CA_OFF   37120
#define CA_SLOT  10560
#define CV_SMEM  142720        // 37120 + 10*10560

__device__ __forceinline__ void cv_stage_row_async(uint32_t sbase, int slot,
                                                   const uint4* __restrict__ src,
                                                   int b, int gy, int x0, int tid) {
    uint32_t d0 = sbase + CA_OFF + slot * CA_SLOT;
    bool rowok = ((unsigned)gy < 256u);
    const uint4* sp = src + (((size_t)(b * 65536 + (rowok ? gy : 0) * 256)) << 3);
    for (int i = tid; i < 528; i += 256) {
        int px = i >> 3, q4 = i & 7;
        int gx = x0 - 1 + px;
        bool ok = rowok && ((unsigned)gx < 256u);
        cp16(d0 + (uint32_t)((px * 40 + q4 * 4) * 4),
             sp + (((ok ? gx : 0)) << 3) + q4, ok ? 16 : 0);
    }
}

__global__ void __launch_bounds__(256, 1)
k_conv_mma(const uint4* __restrict__ srcP, const float* __restrict__ bias,
           float* __restrict__ dstF, uint32_t* __restrict__ dstP,
           const float* __restrict__ xres, int fuse, int convIdx) {
    extern __shared__ char smc[];
    const uint32_t sbase = smem_u32(smc);
    const int tid = threadIdx.x;
    const int wid = tid >> 5;
    const int lane = tid & 31;
    const int g   = lane >> 2;
    const int tig = lane & 3;

    const int nh   = blockIdx.x & 1;
    const int xq   = (blockIdx.x >> 1) & 3;
    const int band = (blockIdx.x >> 3) & 31;
    const int b    = blockIdx.x >> 8;
    const int y0   = band << 3;
    const int x0   = xq << 6;

    // prestage all 10 rows (async) — slots 0..9 for rows y0-1 .. y0+8
#pragma unroll
    for (int r = 0; r < 10; r++)
        cv_stage_row_async(sbase, r, srcP, b, y0 - 1 + r, x0, tid);
    CP_COMMIT();

    if (tid < 64) ((float*)smc)[tid] = bias[tid];
    {
        // paired-nf layout: smem [chunk 36][nfp 2][lane 32] uint4
        const uint4* bsrc = (const uint4*)(g_convB + convIdx * 18432);
        uint4* bdst = (uint4*)(smc + CB_OFF);
        for (int q = tid; q < 2304; q += 256) {
            int c = q >> 6, nfp = (q >> 5) & 1, ln = q & 31;
            bdst[q] = bsrc[c * 128 + (nh * 2 + nfp) * 32 + ln];
        }
    }
    CP_WAIT0();
    __syncthreads();

    const int y = y0 + wid;   // this warp's output row

    float acc[4][4][4];
#pragma unroll
    for (int mf = 0; mf < 4; mf++)
#pragma unroll
        for (int nf = 0; nf < 4; nf++)
#pragma unroll
            for (int r = 0; r < 4; r++) acc[mf][nf][r] = 0.f;

#pragma unroll
    for (int ky = 0; ky < 3; ky++) {
        const char* aSlot = smc + CA_OFF + (wid + ky) * CA_SLOT;
#pragma unroll
        for (int kx = 0; kx < 3; kx++) {
            const int chunk4 = ((ky * 3 + kx) * 4) * 2;   // chunk*2 (uint4 groups of 32)
#pragma unroll
            for (int kc = 0; kc < 4; kc++) {
                uint2 A0[4], A1[4];
#pragma unroll
                for (int mf = 0; mf < 4; mf++) {
                    const char* ab = aSlot + ((mf * 16 + kx + g) * 40 + tig * 2) * 4;
                    A0[mf] = *(const uint2*)(ab + kc * 32);
                    A1[mf] = *(const uint2*)(ab + 8 * 160 + kc * 32);
                }
                const uint4* bq = (const uint4*)(smc + CB_OFF) + (chunk4 + kc * 2) * 32 + lane;
                uint4 B0 = bq[0];
                uint4 B1 = bq[32];
#pragma unroll
                for (int mf = 0; mf < 4; mf++) {
                    mma_fp16(acc[mf][0], A0[mf].x, A1[mf].x, A0[mf].y, A1[mf].y, B0.x, B0.y);
                    mma_fp16(acc[mf][1], A0[mf].x, A1[mf].x, A0[mf].y, A1[mf].y, B0.z, B0.w);
                    mma_fp16(acc[mf][2], A0[mf].x, A1[mf].x, A0[mf].y, A1[mf].y, B1.x, B1.y);
                    mma_fp16(acc[mf][3], A0[mf].x, A1[mf].x, A0[mf].y, A1[mf].y, B1.z, B1.w);
                }
            }
        }
    }

    // epilogue
    {
        const float* bs = (const float*)smc;
#pragma unroll
        for (int mf = 0; mf < 4; mf++) {
            const int pxA = x0 + mf * 16 + g;
            const int pxB = pxA + 8;
            if (fuse) {
                const size_t rowOff = ((size_t)b << 22) + ((size_t)y << 8);
#pragma unroll
                for (int nf = 0; nf < 4; nf++) {
                    int o0 = nh * 32 + nf * 8 + tig * 2;
                    float b0v = bs[o0], b1v = bs[o0 + 1];
                    size_t i00 = rowOff + ((size_t)o0 << 16) + pxA;
                    size_t i01 = rowOff + ((size_t)(o0 + 1) << 16) + pxA;
                    size_t i10 = rowOff + ((size_t)o0 << 16) + pxB;
                    size_t i11 = rowOff + ((size_t)(o0 + 1) << 16) + pxB;
                    float v00 = acc[mf][nf][0] + b0v;
                    float v01 = acc[mf][nf][1] + b1v;
                    float v10 = acc[mf][nf][2] + b0v;
                    float v11 = acc[mf][nf][3] + b1v;
                    float xa = xres[i00], xb2 = xres[i01];
                    float xc = xres[i10], xd = xres[i11];
                    dstF[i00] = v00 * xa + xa;
                    dstF[i01] = v01 * xb2 + xb2;
                    dstF[i10] = v10 * xc + xc;
                    dstF[i11] = v11 * xd + xd;
                }
            } else {
                const size_t rowBase = ((size_t)(b * 65536 + y * 256));
#pragma unroll
                for (int nf = 0; nf < 4; nf++) {
                    int nfg = nh * 4 + nf;
                    int o0 = nfg * 8 + tig * 2;
                    float b0v = bs[o0], b1v = bs[o0 + 1];
                    int w = (nfg >> 1) * 8 + tig * 2 + (nfg & 1);
                    size_t baseA = (rowBase + pxA) * 32 + w;
                    size_t baseB = (rowBase + pxB) * 32 + w;
                    dstP[baseA] = h2pack(acc[mf][nf][0] + b0v, acc[mf][nf][1] + b1v);
                    dstP[baseB] = h2pack(acc[mf][nf][2] + b0v, acc[mf][nf][3] + b1v);
                }
            }
        }
    }
}

// ---------------------------------------------------------------------------
extern "C" void kernel_launch(void* const* d_in, const int* in_sizes, int n_in,
                              void* d_out, int out_size) {
    const float* x  = (const float*)d_in[0];
    const float* Wq = (const float*)d_in[1];
    const float* bq = (const float*)d_in[2];
    const float* Wk = (const float*)d_in[3];
    const float* bk = (const float*)d_in[4];
    const float* Wv = (const float*)d_in[5];
    const float* bv = (const float*)d_in[6];
    const float* Wr = (const float*)d_in[7];
    const float* br = (const float*)d_in[8];
    const float* W1 = (const float*)d_in[9];
    const float* b1 = (const float*)d_in[10];
    const float* W2 = (const float*)d_in[11];
    const float* b2 = (const float*)d_in[12];
    float* out = (float*)d_out;

    cudaFuncSetAttribute(k_qkv,      cudaFuncAttributeMaxDynamicSharedMemorySize, QK_SMEM);
    cudaFuncSetAttribute(k_attn,     cudaFuncAttributeMaxDynamicSharedMemorySize, AT_SMEM);
    cudaFuncSetAttribute(k_conv_mma, cudaFuncAttributeMaxDynamicSharedMemorySize, CV_SMEM);

    void *p_attnP, *p_t1P;
    cudaGetSymbolAddress(&p_attnP, g_attnP);
    cudaGetSymbolAddress(&p_t1P, g_t1P);

    k_prep<<<144, 256>>>(Wq, Wk, Wv, W1, W2, 0);
    k_prep<<<24, 256>>>(Wq, Wk, Wv, W1, W2, 1);
    k_prep<<<2, 256>>>(Wq, Wk, Wv, W1, W2, 2);
    k_qkv<<<1024, 256, QK_SMEM>>>(x, bq, bk, bv, (float*)p_t1P);   // profile slot 3
    k_red<<<128, 256>>>((const float*)p_t1P);
    k_fin<<<32, 256>>>(Wr);
    k_attn<<<4096, 256, AT_SMEM>>>(br);
    k_conv_mma<<<2048, 256, CV_SMEM>>>((const uint4*)p_attnP, b1, nullptr,
                                       (uint32_t*)p_t1P, nullptr, 0, 0);
    k_conv_mma<<<2048, 256, CV_SMEM>>>((const uint4*)p_t1P, b2, out,
                                       nullptr, x, 1, 1);
}

// round 15
// speedup vs baseline: 1.0600x; 1.0600x over previous
#include <cuda_runtime.h>
#include <cuda_fp16.h>
#include <cstdint>

// ---------------------------------------------------------------------------
// HydraAttention_v2 — fully tensorized (mma.sync fp16 m16n8k16), fp16 packed
// fragment-layout intermediates. qkv: 4-chunk persistent blocks. attn: 2-chunk
// persistent blocks. conv: R13 occ-2 tile, cp.async overlap.
// Launches: prep x3 (0-2), qkv(3=profiled), red, fin, attn, conv x2.
// B=8, C=64, H=W=256, N=65536
// ---------------------------------------------------------------------------

#define BATCH 8
#define CH    64
#define NPIX  65536

typedef unsigned long long ull;

__device__ uint32_t g_QnP[BATCH * NPIX * 32];    // packed fp16 Qn
__device__ uint32_t g_attnP[BATCH * NPIX * 32];  // packed fp16 attn
__device__ uint32_t g_t1P[BATCH * NPIX * 32];    // conv1 out; BEFORE conv1: qkv aggkv scratch
__device__ float    g_ksum[BATCH * CH];
__device__ float    g_vsum[BATCH * CH];
__device__ float    g_aggkv[BATCH * CH * CH];
__device__ float    g_wrvs[BATCH * CH];
__device__ uint32_t g_M2h[BATCH * 2048];         // packed fp16 M2 B-frags
__device__ uint32_t g_qkvB[6144];                // packed fp16 QKV weights
__device__ uint32_t g_convB[2 * 36 * 64 * 8];    // packed fp16 conv weights

// ---- helpers ----------------------------------------------------------------
__device__ __forceinline__ void mma_fp16(float c[4], uint32_t a0, uint32_t a1,
                                         uint32_t a2, uint32_t a3,
                                         uint32_t b0, uint32_t b1) {
    asm volatile(
        "mma.sync.aligned.m16n8k16.row.col.f32.f16.f16.f32 "
        "{%0,%1,%2,%3}, {%4,%5,%6,%7}, {%8,%9}, {%0,%1,%2,%3};"
        : "+f"(c[0]), "+f"(c[1]), "+f"(c[2]), "+f"(c[3])
        : "r"(a0), "r"(a1), "r"(a2), "r"(a3), "r"(b0), "r"(b1));
}
__device__ __forceinline__ uint32_t h2pack(float a, float b) {
    __half2 h = __float22half2_rn(make_float2(a, b));
    return *(uint32_t*)&h;
}
__device__ __forceinline__ float2 h2up(uint32_t w) {
    __half2 h = *(__half2*)&w;
    return __half22float2(h);
}
__device__ __forceinline__ uint32_t smem_u32(const void* p) {
    uint32_t a;
    asm("{ .reg .u64 t; cvta.to.shared.u64 t, %1; cvt.u32.u64 %0, t; }" : "=r"(a) : "l"(p));
    return a;
}
__device__ __forceinline__ void cp16(uint32_t dst, const void* src, int sz) {
    asm volatile("cp.async.ca.shared.global [%0], [%1], 16, %2;"
                 :: "r"(dst), "l"(src), "r"(sz) : "memory");
}
#define CP_COMMIT() asm volatile("cp.async.commit_group;" ::: "memory")
#define CP_WAIT0()  asm volatile("cp.async.wait_group 0;" ::: "memory")

// ---------------------------------------------------------------------------
// prep phases: 0 = conv weights, 1 = qkv weights, 2 = zero sums
__global__ void k_prep(const float* __restrict__ Wq, const float* __restrict__ Wk,
                       const float* __restrict__ Wv,
                       const float* __restrict__ W1, const float* __restrict__ W2,
                       int phase) {
    int i = blockIdx.x * 256 + threadIdx.x;
    if (phase == 0) {
        if (i >= 36864) return;
        int conv = i / 18432;
        int r    = i % 18432;
        int chunk = r >> 9;
        int w     = r & 511;
        int n   = w >> 3;
        int ww  = w & 7;
        int tig = ww >> 1, s = ww & 1;
        int tap = chunk >> 2, kc = chunk & 3;
        int ch = kc * 16 + 2 * tig + 8 * s;
        const float* W = conv ? W2 : W1;
        g_convB[i] = h2pack(W[n * 576 + ch * 9 + tap], W[n * 576 + (ch + 1) * 9 + tap]);
    } else if (phase == 1) {
        if (i >= 6144) return;
        int s = i & 1, tig = (i >> 1) & 3, g = (i >> 3) & 7;
        int nf = (i >> 6) % 24, kc = i / (64 * 24);
        int n = nf * 8 + g;
        int ch = kc * 16 + tig * 2 + s * 8;
        const float* W; int row;
        if (n < 64)       { W = Wq; row = n; }
        else if (n < 96)  { W = Wv; row = n - 64; }
        else if (n < 160) { W = Wk; row = n - 96; }
        else              { W = Wv; row = n - 128; }
        g_qkvB[i] = h2pack(W[row * 64 + ch], W[row * 64 + ch + 1]);
    } else {
        if (i < 512) { g_ksum[i] = 0.f; g_vsum[i] = 0.f; }
    }
}

// ---------------------------------------------------------------------------
// k_qkv: 1024 blocks, each processes 4 chunks of 128 px. (R13)
#define QK_XA   0
#define QK_B    20480
#define QK_KN   45056
#define QK_V    62464
#define QK_QN   79872
#define QK_SMEM 96768

__global__ void __launch_bounds__(256, 2)
k_qkv(const float* __restrict__ x, const float* __restrict__ bq,
      const float* __restrict__ bk, const float* __restrict__ bv,
      float* __restrict__ gpart) {
    extern __shared__ char sm[];
    uint32_t* Bw  = (uint32_t*)(sm + QK_B);
    __half*   knh = (__half*)(sm + QK_KN);
    __half*   vh  = (__half*)(sm + QK_V);
    uint32_t* qn  = (uint32_t*)(sm + QK_QN);

    const int tid = threadIdx.x;
    const int b   = blockIdx.x >> 7;
    const int seg = blockIdx.x & 127;

    for (int i = tid; i < 6144; i += 256) Bw[i] = g_qkvB[i];

    const int wid = tid >> 5, lane = tid & 31;
    const int g = lane >> 2, tig = lane & 3;
    const int pxq = wid & 3, nh = wid >> 2;
    const int px0 = pxq << 5;
    const int mt = wid & 3, nh2 = wid >> 2;

    float ag[4][4];
#pragma unroll
    for (int nf = 0; nf < 4; nf++)
#pragma unroll
        for (int r = 0; r < 4; r++) ag[nf][r] = 0.f;
    float ksacc = 0.f;

#pragma unroll 1
    for (int c = 0; c < 4; c++) {
        const int n0 = ((seg << 2) + c) << 7;

        {
            const float* xb = x + ((size_t)b << 22) + n0;
            uint32_t* xa = (uint32_t*)(sm + QK_XA);
            for (int i = tid; i < 4096; i += 256) {
                int px = i & 127, p = i >> 7;
                float f0 = __ldg(xb + ((size_t)(2 * p) << 16) + px);
                float f1 = __ldg(xb + ((size_t)(2 * p + 1) << 16) + px);
                int kc = p >> 3, t3 = p & 7;
                int w = kc * 8 + (t3 & 3) * 2 + (t3 >> 2);
                xa[px * 40 + w] = h2pack(f0, f1);
            }
        }
        __syncthreads();

#pragma unroll 1
        for (int mf = 0; mf < 2; mf++) {
            float acc[12][4];
#pragma unroll
            for (int nf = 0; nf < 12; nf++)
#pragma unroll
                for (int r = 0; r < 4; r++) acc[nf][r] = 0.f;

#pragma unroll
            for (int kc = 0; kc < 4; kc++) {
                const char* ab = sm + QK_XA + ((px0 + mf * 16 + g) * 40 + tig * 2) * 4;
                uint2 A0 = *(const uint2*)(ab + kc * 32);
                uint2 A1 = *(const uint2*)(ab + 8 * 160 + kc * 32);
#pragma unroll
                for (int nf = 0; nf < 12; nf++) {
                    int nfg = nh * 12 + nf;
                    uint2 Bv = *(const uint2*)((const char*)Bw +
                                ((kc * 24 + nfg) * 64 + g * 8 + tig * 2) * 4);
                    mma_fp16(acc[nf], A0.x, A1.x, A0.y, A1.y, Bv.x, Bv.y);
                }
            }

#pragma unroll
            for (int nf = 0; nf < 12; nf++) {
                float2 bb;
                if (nh == 0) bb = (nf < 8) ? *(const float2*)(bq + nf * 8 + tig * 2)
                                           : *(const float2*)(bv + (nf - 8) * 8 + tig * 2);
                else         bb = (nf < 8) ? *(const float2*)(bk + nf * 8 + tig * 2)
                                           : *(const float2*)(bv + 32 + (nf - 8) * 8 + tig * 2);
                acc[nf][0] += bb.x; acc[nf][1] += bb.y;
                acc[nf][2] += bb.x; acc[nf][3] += bb.y;
            }

            float ss0 = 0.f, ss1 = 0.f;
#pragma unroll
            for (int nf = 0; nf < 8; nf++) {
                ss0 += acc[nf][0] * acc[nf][0] + acc[nf][1] * acc[nf][1];
                ss1 += acc[nf][2] * acc[nf][2] + acc[nf][3] * acc[nf][3];
            }
            ss0 += __shfl_xor_sync(0xffffffffu, ss0, 1);
            ss0 += __shfl_xor_sync(0xffffffffu, ss0, 2);
            ss1 += __shfl_xor_sync(0xffffffffu, ss1, 1);
            ss1 += __shfl_xor_sync(0xffffffffu, ss1, 2);
            float inv0 = rsqrtf(ss0), inv1 = rsqrtf(ss1);
            const int pxA = px0 + mf * 16 + g, pxB = pxA + 8;

            if (nh == 0) {
#pragma unroll
                for (int nf = 0; nf < 8; nf++) {
                    int w = (nf >> 1) * 8 + tig * 2 + (nf & 1);
                    qn[pxA * 33 + w] = h2pack(acc[nf][0] * inv0, acc[nf][1] * inv0);
                    qn[pxB * 33 + w] = h2pack(acc[nf][2] * inv1, acc[nf][3] * inv1);
                }
            } else {
#pragma unroll
                for (int nf = 0; nf < 8; nf++) {
                    int m = nf * 8 + tig * 2;
                    knh[m * 136 + pxA]       = __float2half(acc[nf][0] * inv0);
                    knh[(m + 1) * 136 + pxA] = __float2half(acc[nf][1] * inv0);
                    knh[m * 136 + pxB]       = __float2half(acc[nf][2] * inv1);
                    knh[(m + 1) * 136 + pxB] = __float2half(acc[nf][3] * inv1);
                }
            }
#pragma unroll
            for (int nf = 8; nf < 12; nf++) {
                int cc = (nh ? 32 : 0) + (nf - 8) * 8 + tig * 2;
                vh[cc * 136 + pxA]       = __float2half(acc[nf][0]);
                vh[(cc + 1) * 136 + pxA] = __float2half(acc[nf][1]);
                vh[cc * 136 + pxB]       = __float2half(acc[nf][2]);
                vh[(cc + 1) * 136 + pxB] = __float2half(acc[nf][3]);
            }
        }
        __syncthreads();

        {
            uint32_t* gq = g_QnP + (((size_t)b << 16) + n0) * 32;
            for (int j = tid; j < 4096; j += 256)
                gq[j] = qn[(j >> 5) * 33 + (j & 31)];
        }

        if (tid < 128) {
            const uint32_t* rw = (tid < 64)
                ? (const uint32_t*)(sm + QK_KN) + tid * 68
                : (const uint32_t*)(sm + QK_V) + (tid - 64) * 68;
#pragma unroll 8
            for (int j = 0; j < 64; j++) { float2 f = h2up(rw[j]); ksacc += f.x + f.y; }
        }

        {
            const uint32_t* knw = (const uint32_t*)(sm + QK_KN);
            const uint32_t* vw  = (const uint32_t*)(sm + QK_V);
#pragma unroll
            for (int kc = 0; kc < 8; kc++) {
                int ra = (mt * 16 + g) * 68 + kc * 8 + tig;
                uint32_t a0 = knw[ra],          a2 = knw[ra + 4];
                uint32_t a1 = knw[ra + 8 * 68], a3 = knw[ra + 8 * 68 + 4];
#pragma unroll
                for (int nf = 0; nf < 4; nf++) {
                    int rb = (nh2 * 32 + nf * 8 + g) * 68 + kc * 8 + tig;
                    mma_fp16(ag[nf], a0, a1, a2, a3, vw[rb], vw[rb + 4]);
                }
            }
        }
        __syncthreads();
    }

    if (tid < 128) {
        float* dp = (tid < 64) ? &g_ksum[b * 64 + tid] : &g_vsum[b * 64 + tid - 64];
        atomicAdd(dp, ksacc);
    }

    {
        float* agg_s = (float*)(sm + QK_XA);
#pragma unroll
        for (int nf = 0; nf < 4; nf++) {
            int r0 = (mt * 16 + g) * 66 + nh2 * 32 + nf * 8 + tig * 2;
            *(float2*)&agg_s[r0]          = make_float2(ag[nf][0], ag[nf][1]);
            *(float2*)&agg_s[r0 + 8 * 66] = make_float2(ag[nf][2], ag[nf][3]);
        }
        __syncthreads();
        float* gp = gpart + (size_t)blockIdx.x * 4096;
        for (int j = tid; j < 4096; j += 256)
            gp[j] = agg_s[(j >> 6) * 66 + (j & 63)];
    }
}

// ---------------------------------------------------------------------------
__global__ void __launch_bounds__(256, 1)
k_red(const float* __restrict__ gpart) {
    int e = blockIdx.x * 256 + threadIdx.x;
    int b = e >> 12, idx = e & 4095;
    const float* p = gpart + ((size_t)b * 128) * 4096 + idx;
    float s0 = 0.f, s1 = 0.f, s2 = 0.f, s3 = 0.f;
#pragma unroll 4
    for (int q = 0; q < 128; q += 4) {
        s0 += p[(size_t)q * 4096];
        s1 += p[(size_t)(q + 1) * 4096];
        s2 += p[(size_t)(q + 2) * 4096];
        s3 += p[(size_t)(q + 3) * 4096];
    }
    g_aggkv[e] = (s0 + s1) + (s2 + s3);
}

// ---------------------------------------------------------------------------
__global__ void __launch_bounds__(256, 1)
k_fin(const float* __restrict__ Wr) {
    __shared__ float a_s[1024];
    __shared__ float w_s[4096];
    __shared__ float vs_s[64];

    int b  = blockIdx.x >> 2;
    int mq = blockIdx.x & 3;
    int tid = threadIdx.x;

    for (int idx = tid; idx < 4096; idx += 256) {
        int o = idx & 63, c = idx >> 6;
        w_s[c * 64 + o] = Wr[o * 64 + c];
    }
    for (int idx = tid; idx < 1024; idx += 256)
        a_s[idx] = g_aggkv[b * 4096 + mq * 1024 + idx];
    if (tid < 64) vs_s[tid] = g_vsum[b * 64 + tid];
    __syncthreads();

    int o = tid & 63, sub = tid >> 6;
    if (mq == 0 && sub == 0) {
        float s = 0.f;
#pragma unroll 8
        for (int c = 0; c < 64; c++) s += w_s[c * 64 + o] * vs_s[c];
        g_wrvs[b * 64 + o] = s;
    }
    int nf = o >> 3, gg = o & 7;
#pragma unroll
    for (int ml = sub * 4; ml < sub * 4 + 4; ml += 2) {
        int m = mq * 16 + ml;
        float t0 = 0.f, t1 = 0.f;
#pragma unroll 8
        for (int c = 0; c < 64; c++) {
            t0 += w_s[c * 64 + o] * a_s[ml * 64 + c];
            t1 += w_s[c * 64 + o] * a_s[(ml + 1) * 64 + c];
        }
        int kc = m >> 4, r = m & 15;
        int s2 = r >> 3, tg = (r & 7) >> 1;
        g_M2h[b * 2048 + ((kc * 8 + nf) * 64 + gg * 8 + tg * 2 + s2)] = h2pack(t0, t1);
    }
}

// ---------------------------------------------------------------------------
// k_attn: 2048 blocks; each handles 2 chunks of 128 px; M2/ks/wv/br staged once.
#define AT_QN   0
#define AT_M2   20480
#define AT_KS   28672
#define AT_WV   28928
#define AT_BR   29184
#define AT_SMEM 29440

__global__ void __launch_bounds__(256, 3)
k_attn(const float* __restrict__ br) {
    extern __shared__ char sm[];
    uint32_t* m2  = (uint32_t*)(sm + AT_M2);
    float*    ks  = (float*)(sm + AT_KS);
    float*    wv  = (float*)(sm + AT_WV);
    float*    brs = (float*)(sm + AT_BR);

    const int tid = threadIdx.x;
    const int b   = blockIdx.x >> 8;
    const int seg = blockIdx.x & 255;

    for (int i = tid; i < 2048; i += 256) m2[i] = g_M2h[b * 2048 + i];
    if (tid < 64) {
        ks[tid]  = g_ksum[b * 64 + tid] + 1e-6f;
        wv[tid]  = g_wrvs[b * 64 + tid];
        brs[tid] = __ldg(&br[tid]);
    }

    const int wid = tid >> 5, lane = tid & 31;
    const int g = lane >> 2, tig = lane & 3;
    const int px0 = wid << 4;

#pragma unroll 1
    for (int c = 0; c < 2; c++) {
        const int n0 = ((seg << 1) + c) << 7;

        {
            const uint4* gq = (const uint4*)(g_QnP + (((size_t)b << 16) + n0) * 32);
            for (int i = tid; i < 1024; i += 256) {
                int px = i >> 3, q4 = i & 7;
                *(uint4*)(sm + (px * 40 + q4 * 4) * 4) = __ldg(gq + px * 8 + q4);
            }
        }
        __syncthreads();

        float acc[8][4];
#pragma unroll
        for (int nf = 0; nf < 8; nf++)
#pragma unroll
            for (int r = 0; r < 4; r++) acc[nf][r] = 0.f;
        float dot0 = 0.f, dot1 = 0.f;

#pragma unroll
        for (int kc = 0; kc < 4; kc++) {
            const char* ab = sm + ((px0 + g) * 40 + tig * 2) * 4;
            uint2 A0 = *(const uint2*)(ab + kc * 32);
            uint2 A1 = *(const uint2*)(ab + 8 * 160 + kc * 32);
            float2 ka = *(const float2*)&ks[kc * 16 + tig * 2];
            float2 kb = *(const float2*)&ks[kc * 16 + tig * 2 + 8];
            float2 f;
            f = h2up(A0.x); dot0 += f.x * ka.x + f.y * ka.y;
            f = h2up(A0.y); dot0 += f.x * kb.x + f.y * kb.y;
            f = h2up(A1.x); dot1 += f.x * ka.x + f.y * ka.y;
            f = h2up(A1.y); dot1 += f.x * kb.x + f.y * kb.y;
#pragma unroll
            for (int nf = 0; nf < 8; nf++) {
                uint2 Bv = *(const uint2*)((const char*)m2 +
                            ((kc * 8 + nf) * 64 + g * 8 + tig * 2) * 4);
                mma_fp16(acc[nf], A0.x, A1.x, A0.y, A1.y, Bv.x, Bv.y);
            }
        }
        dot0 += __shfl_xor_sync(0xffffffffu, dot0, 1);
        dot0 += __shfl_xor_sync(0xffffffffu, dot0, 2);
        dot1 += __shfl_xor_sync(0xffffffffu, dot1, 1);
        dot1 += __shfl_xor_sync(0xffffffffu, dot1, 2);
        float den0 = 1.f / (65536.f + dot0);
        float den1 = 1.f / (65536.f + dot1);

        uint32_t* ga = g_attnP + (((size_t)b << 16) + n0) * 32;
#pragma unroll
        for (int nf = 0; nf < 8; nf++) {
            int o = nf * 8 + tig * 2;
            int w = (nf >> 1) * 8 + tig * 2 + (nf & 1);
            float v0 = brs[o]     + den0 * (wv[o]     + acc[nf][0]);
            float v1 = brs[o + 1] + den0 * (wv[o + 1] + acc[nf][1]);
            float v2 = brs[o]     + den1 * (wv[o]     + acc[nf][2]);
            float v3 = brs[o + 1] + den1 * (wv[o + 1] + acc[nf][3]);
            ga[(px0 + g) * 32 + w]     = h2pack(v0, v1);
            ga[(px0 + g + 8) * 32 + w] = h2pack(v2, v3);
        }
        __syncthreads();   // Qn reads done before next chunk overwrites
    }
}

// ---------------------------------------------------------------------------
// conv3x3 via mma.sync fp16, occ 2, cp.async staging overlapped with epilogue.
// (R13 winner, unchanged)
#define CB_OFF   256
#define CA_OFF   37120
#define CA_SLOT  10560
#define CV_SMEM  100480

__device__ __forceinline__ void cv_stage_row_async(uint32_t sbase, int slot,
                                                   const uint4* __restrict__ src,
                                                   int b, int gy, int x0, int tid) {
    uint32_t d0 = sbase + CA_OFF + slot * CA_SLOT;
    bool rowok = ((unsigned)gy < 256u);
    const uint4* sp = src + (((size_t)(b * 65536 + (rowok ? gy : 0) * 256)) << 3);
    for (int i = tid; i < 528; i += 256) {
        int px = i >> 3, q4 = i & 7;
        int gx = x0 - 1 + px;
        bool ok = rowok && ((unsigned)gx < 256u);
        cp16(d0 + (uint32_t)((px * 40 + q4 * 4) * 4),
             sp + (((ok ? gx : 0)) << 3) + q4, ok ? 16 : 0);
    }
}

__global__ void __launch_bounds__(256, 2)
k_conv_mma(const uint4* __restrict__ srcP, const float* __restrict__ bias,
           float* __restrict__ dstF, uint32_t* __restrict__ dstP,
           const float* __restrict__ xres, int fuse, int convIdx) {
    extern __shared__ char smc[];
    const uint32_t sbase = smem_u32(smc);
    const int tid = threadIdx.x;
    const int wid = tid >> 5;
    const int lane = tid & 31;
    const int g   = lane >> 2;
    const int tig = lane & 3;

    const int nh   = blockIdx.x & 1;
    const int xq   = (blockIdx.x >> 1) & 3;
    const int band = (blockIdx.x >> 3) & 31;
    const int b    = blockIdx.x >> 8;
    const int y0   = band << 3;
    const int x0   = xq << 6;

    if (tid < 64) ((float*)smc)[tid] = bias[tid];
    {
        const uint4* bsrc = (const uint4*)(g_convB + convIdx * 18432);
        uint4* bdst = (uint4*)(smc + CB_OFF);
        for (int q = tid; q < 2304; q += 256) {
            int c = q >> 6, j = q & 63;
            bdst[q] = bsrc[c * 128 + nh * 64 + j];
        }
    }

    cv_stage_row_async(sbase, (y0)     % 6, srcP, b, y0 - 1, x0, tid);
    cv_stage_row_async(sbase, (y0 + 1) % 6, srcP, b, y0,     x0, tid);
    cv_stage_row_async(sbase, (y0 + 2) % 6, srcP, b, y0 + 1, x0, tid);
    cv_stage_row_async(sbase, (y0 + 3) % 6, srcP, b, y0 + 2, x0, tid);
    cv_stage_row_async(sbase, (y0 + 4) % 6, srcP, b, y0 + 3, x0, tid);
    cv_stage_row_async(sbase, (y0 + 5) % 6, srcP, b, y0 + 4, x0, tid);
    CP_COMMIT();
    CP_WAIT0();
    __syncthreads();

    const int rsel = wid >> 1;
    const int px0  = (wid & 1) << 5;

    for (int t = 0; t < 8; t += 4) {
        const int y = y0 + t + rsel;

        float acc[2][4][4];
#pragma unroll
        for (int mf = 0; mf < 2; mf++)
#pragma unroll
            for (int nf = 0; nf < 4; nf++)
#pragma unroll
                for (int r = 0; r < 4; r++) acc[mf][nf][r] = 0.f;

#pragma unroll
        for (int ky = 0; ky < 3; ky++) {
            const char* aSlot = smc + CA_OFF + ((y + ky) % 6) * CA_SLOT;
#pragma unroll
            for (int kx = 0; kx < 3; kx++) {
                const char* aBase0 = aSlot + ((px0 + kx + g) * 40 + tig * 2) * 4;
                const char* aBase1 = aSlot + ((px0 + 16 + kx + g) * 40 + tig * 2) * 4;
                const char* bTap   = smc + CB_OFF + (ky * 3 + kx) * 4096
                                     + (g * 8 + tig * 2) * 4;
#pragma unroll
                for (int kc = 0; kc < 4; kc++) {
                    uint2 A0 = *(const uint2*)(aBase0 + kc * 32);
                    uint2 A1 = *(const uint2*)(aBase0 + 8 * 160 + kc * 32);
                    uint2 A2 = *(const uint2*)(aBase1 + kc * 32);
                    uint2 A3 = *(const uint2*)(aBase1 + 8 * 160 + kc * 32);
                    const char* bc = bTap + kc * 1024;
#pragma unroll
                    for (int nf = 0; nf < 4; nf++) {
                        uint2 B = *(const uint2*)(bc + nf * 256);
                        mma_fp16(acc[0][nf], A0.x, A1.x, A0.y, A1.y, B.x, B.y);
                        mma_fp16(acc[1][nf], A2.x, A3.x, A2.y, A3.y, B.x, B.y);
                    }
                }
            }
        }

        if (t == 0) {
            __syncthreads();
            cv_stage_row_async(sbase, (y0 + 6) % 6, srcP, b, y0 + 5, x0, tid);
            cv_stage_row_async(sbase, (y0 + 7) % 6, srcP, b, y0 + 6, x0, tid);
            cv_stage_row_async(sbase, (y0 + 8) % 6, srcP, b, y0 + 7, x0, tid);
            cv_stage_row_async(sbase, (y0 + 9) % 6, srcP, b, y0 + 8, x0, tid);
            CP_COMMIT();
        }

        {
            const float* bs = (const float*)smc;
#pragma unroll
            for (int mf = 0; mf < 2; mf++) {
                const int pxA = x0 + px0 + mf * 16 + g;
                const int pxB = pxA + 8;
                if (fuse) {
                    const size_t rowOff = ((size_t)b << 22) + ((size_t)y << 8);
#pragma unroll
                    for (int nf = 0; nf < 4; nf++) {
                        int o0 = nh * 32 + nf * 8 + tig * 2;
                        float b0v = bs[o0], b1v = bs[o0 + 1];
                        size_t i00 = rowOff + ((size_t)o0 << 16) + pxA;
                        size_t i01 = rowOff + ((size_t)(o0 + 1) << 16) + pxA;
                        size_t i10 = rowOff + ((size_t)o0 << 16) + pxB;
                        size_t i11 = rowOff + ((size_t)(o0 + 1) << 16) + pxB;
                        float v00 = acc[mf][nf][0] + b0v;
                        float v01 = acc[mf][nf][1] + b1v;
                        float v10 = acc[mf][nf][2] + b0v;
                        float v11 = acc[mf][nf][3] + b1v;
                        float xa = xres[i00], xb2 = xres[i01];
                        float xc = xres[i10], xd = xres[i11];
                        dstF[i00] = v00 * xa + xa;
                        dstF[i01] = v01 * xb2 + xb2;
                        dstF[i10] = v10 * xc + xc;
                        dstF[i11] = v11 * xd + xd;
                    }
                } else {
                    const size_t rowBase = ((size_t)(b * 65536 + y * 256));
#pragma unroll
                    for (int nf = 0; nf < 4; nf++) {
                        int nfg = nh * 4 + nf;
                        int o0 = nfg * 8 + tig * 2;
                        float b0v = bs[o0], b1v = bs[o0 + 1];
                        int w = (nfg >> 1) * 8 + tig * 2 + (nfg & 1);
                        size_t baseA = (rowBase + pxA) * 32 + w;
                        size_t baseB = (rowBase + pxB) * 32 + w;
                        dstP[baseA] = h2pack(acc[mf][nf][0] + b0v, acc[mf][nf][1] + b1v);
                        dstP[baseB] = h2pack(acc[mf][nf][2] + b0v, acc[mf][nf][3] + b1v);
                    }
                }
            }
        }

        if (t == 0) {
            CP_WAIT0();
            __syncthreads();
        }
    }
}

// ---------------------------------------------------------------------------
extern "C" void kernel_launch(void* const* d_in, const int* in_sizes, int n_in,
                              void* d_out, int out_size) {
    const float* x  = (const float*)d_in[0];
    const float* Wq = (const float*)d_in[1];
    const float* bq = (const float*)d_in[2];
    const float* Wk = (const float*)d_in[3];
    const float* bk = (const float*)d_in[4];
    const float* Wv = (const float*)d_in[5];
    const float* bv = (const float*)d_in[6];
    const float* Wr = (const float*)d_in[7];
    const float* br = (const float*)d_in[8];
    const float* W1 = (const float*)d_in[9];
    const float* b1 = (const float*)d_in[10];
    const float* W2 = (const float*)d_in[11];
    const float* b2 = (const float*)d_in[12];
    float* out = (float*)d_out;

    cudaFuncSetAttribute(k_qkv,      cudaFuncAttributeMaxDynamicSharedMemorySize, QK_SMEM);
    cudaFuncSetAttribute(k_attn,     cudaFuncAttributeMaxDynamicSharedMemorySize, AT_SMEM);
    cudaFuncSetAttribute(k_conv_mma, cudaFuncAttributeMaxDynamicSharedMemorySize, CV_SMEM);

    void *p_attnP, *p_t1P;
    cudaGetSymbolAddress(&p_attnP, g_attnP);
    cudaGetSymbolAddress(&p_t1P, g_t1P);

    k_prep<<<144, 256>>>(Wq, Wk, Wv, W1, W2, 0);
    k_prep<<<24, 256>>>(Wq, Wk, Wv, W1, W2, 1);
    k_prep<<<2, 256>>>(Wq, Wk, Wv, W1, W2, 2);
    k_qkv<<<1024, 256, QK_SMEM>>>(x, bq, bk, bv, (float*)p_t1P);   // profile slot 3
    k_red<<<128, 256>>>((const float*)p_t1P);
    k_fin<<<32, 256>>>(Wr);
    k_attn<<<2048, 256, AT_SMEM>>>(br);
    k_conv_mma<<<2048, 256, CV_SMEM>>>((const uint4*)p_attnP, b1, nullptr,
                                       (uint32_t*)p_t1P, nullptr, 0, 0);
    k_conv_mma<<<2048, 256, CV_SMEM>>>((const uint4*)p_t1P, b2, out,
                                       nullptr, x, 1, 1);
}

// round 16
// speedup vs baseline: 1.0958x; 1.0338x over previous
#include <cuda_runtime.h>
#include <cuda_fp16.h>
#include <cstdint>

// ---------------------------------------------------------------------------
// HydraAttention_v2 — fully tensorized (mma.sync fp16 m16n8k16), fp16 packed
// fragment-layout intermediates. qkv: 4-chunk persistent blocks. attn: 4-chunk
// persistent blocks. conv: occ-2 tile, cp.async overlap, paired-nf LDS.128 B.
// Launches: prep x3 (0-2), qkv(3=profiled), red, fin, attn, conv x2.
// B=8, C=64, H=W=256, N=65536
// ---------------------------------------------------------------------------

#define BATCH 8
#define CH    64
#define NPIX  65536

typedef unsigned long long ull;

__device__ uint32_t g_QnP[BATCH * NPIX * 32];    // packed fp16 Qn
__device__ uint32_t g_attnP[BATCH * NPIX * 32];  // packed fp16 attn
__device__ uint32_t g_t1P[BATCH * NPIX * 32];    // conv1 out; BEFORE conv1: qkv aggkv scratch
__device__ float    g_ksum[BATCH * CH];
__device__ float    g_vsum[BATCH * CH];
__device__ float    g_aggkv[BATCH * CH * CH];
__device__ float    g_wrvs[BATCH * CH];
__device__ uint32_t g_M2h[BATCH * 2048];         // packed fp16 M2 B-frags
__device__ uint32_t g_qkvB[6144];                // packed fp16 QKV weights
__device__ uint32_t g_convB[2 * 36 * 512];       // packed fp16 conv weights (paired-nf)

// ---- helpers ----------------------------------------------------------------
__device__ __forceinline__ void mma_fp16(float c[4], uint32_t a0, uint32_t a1,
                                         uint32_t a2, uint32_t a3,
                                         uint32_t b0, uint32_t b1) {
    asm volatile(
        "mma.sync.aligned.m16n8k16.row.col.f32.f16.f16.f32 "
        "{%0,%1,%2,%3}, {%4,%5,%6,%7}, {%8,%9}, {%0,%1,%2,%3};"
        : "+f"(c[0]), "+f"(c[1]), "+f"(c[2]), "+f"(c[3])
        : "r"(a0), "r"(a1), "r"(a2), "r"(a3), "r"(b0), "r"(b1));
}
__device__ __forceinline__ uint32_t h2pack(float a, float b) {
    __half2 h = __float22half2_rn(make_float2(a, b));
    return *(uint32_t*)&h;
}
__device__ __forceinline__ float2 h2up(uint32_t w) {
    __half2 h = *(__half2*)&w;
    return __half22float2(h);
}
__device__ __forceinline__ uint32_t smem_u32(const void* p) {
    uint32_t a;
    asm("{ .reg .u64 t; cvta.to.shared.u64 t, %1; cvt.u32.u64 %0, t; }" : "=r"(a) : "l"(p));
    return a;
}
__device__ __forceinline__ void cp16(uint32_t dst, const void* src, int sz) {
    asm volatile("cp.async.ca.shared.global [%0], [%1], 16, %2;"
                 :: "r"(dst), "l"(src), "r"(sz) : "memory");
}
#define CP_COMMIT() asm volatile("cp.async.commit_group;" ::: "memory")
#define CP_WAIT0()  asm volatile("cp.async.wait_group 0;" ::: "memory")

// ---------------------------------------------------------------------------
// prep phases: 0 = conv weights (paired-nf, R14-verified layout), 1 = qkv, 2 = zeros
__global__ void k_prep(const float* __restrict__ Wq, const float* __restrict__ Wk,
                       const float* __restrict__ Wv,
                       const float* __restrict__ W1, const float* __restrict__ W2,
                       int phase) {
    int i = blockIdx.x * 256 + threadIdx.x;
    if (phase == 0) {
        if (i >= 36864) return;
        int conv = i / 18432;
        int r    = i % 18432;
        int chunk = r >> 9;
        int w     = r & 511;
        int nfp = w >> 7;
        int lt  = (w >> 2) & 31;
        int j   = (w >> 1) & 1;
        int s   = w & 1;
        int g = lt >> 2, tig = lt & 3;
        int nf = 2 * nfp + j;
        int n  = nf * 8 + g;
        int tap = chunk >> 2, kc = chunk & 3;
        int ch = kc * 16 + tig * 2 + s * 8;
        const float* W = conv ? W2 : W1;
        g_convB[i] = h2pack(W[n * 576 + ch * 9 + tap], W[n * 576 + (ch + 1) * 9 + tap]);
    } else if (phase == 1) {
        if (i >= 6144) return;
        int s = i & 1, tig = (i >> 1) & 3, g = (i >> 3) & 7;
        int nf = (i >> 6) % 24, kc = i / (64 * 24);
        int n = nf * 8 + g;
        int ch = kc * 16 + tig * 2 + s * 8;
        const float* W; int row;
        if (n < 64)       { W = Wq; row = n; }
        else if (n < 96)  { W = Wv; row = n - 64; }
        else if (n < 160) { W = Wk; row = n - 96; }
        else              { W = Wv; row = n - 128; }
        g_qkvB[i] = h2pack(W[row * 64 + ch], W[row * 64 + ch + 1]);
    } else {
        if (i < 512) { g_ksum[i] = 0.f; g_vsum[i] = 0.f; }
    }
}

// ---------------------------------------------------------------------------
// k_qkv: 1024 blocks, each processes 4 chunks of 128 px. (R13, unchanged)
#define QK_XA   0
#define QK_B    20480
#define QK_KN   45056
#define QK_V    62464
#define QK_QN   79872
#define QK_SMEM 96768

__global__ void __launch_bounds__(256, 2)
k_qkv(const float* __restrict__ x, const float* __restrict__ bq,
      const float* __restrict__ bk, const float* __restrict__ bv,
      float* __restrict__ gpart) {
    extern __shared__ char sm[];
    uint32_t* Bw  = (uint32_t*)(sm + QK_B);
    __half*   knh = (__half*)(sm + QK_KN);
    __half*   vh  = (__half*)(sm + QK_V);
    uint32_t* qn  = (uint32_t*)(sm + QK_QN);

    const int tid = threadIdx.x;
    const int b   = blockIdx.x >> 7;
    const int seg = blockIdx.x & 127;

    for (int i = tid; i < 6144; i += 256) Bw[i] = g_qkvB[i];

    const int wid = tid >> 5, lane = tid & 31;
    const int g = lane >> 2, tig = lane & 3;
    const int pxq = wid & 3, nh = wid >> 2;
    const int px0 = pxq << 5;
    const int mt = wid & 3, nh2 = wid >> 2;

    float ag[4][4];
#pragma unroll
    for (int nf = 0; nf < 4; nf++)
#pragma unroll
        for (int r = 0; r < 4; r++) ag[nf][r] = 0.f;
    float ksacc = 0.f;

#pragma unroll 1
    for (int c = 0; c < 4; c++) {
        const int n0 = ((seg << 2) + c) << 7;

        {
            const float* xb = x + ((size_t)b << 22) + n0;
            uint32_t* xa = (uint32_t*)(sm + QK_XA);
            for (int i = tid; i < 4096; i += 256) {
                int px = i & 127, p = i >> 7;
                float f0 = __ldg(xb + ((size_t)(2 * p) << 16) + px);
                float f1 = __ldg(xb + ((size_t)(2 * p + 1) << 16) + px);
                int kc = p >> 3, t3 = p & 7;
                int w = kc * 8 + (t3 & 3) * 2 + (t3 >> 2);
                xa[px * 40 + w] = h2pack(f0, f1);
            }
        }
        __syncthreads();

#pragma unroll 1
        for (int mf = 0; mf < 2; mf++) {
            float acc[12][4];
#pragma unroll
            for (int nf = 0; nf < 12; nf++)
#pragma unroll
                for (int r = 0; r < 4; r++) acc[nf][r] = 0.f;

#pragma unroll
            for (int kc = 0; kc < 4; kc++) {
                const char* ab = sm + QK_XA + ((px0 + mf * 16 + g) * 40 + tig * 2) * 4;
                uint2 A0 = *(const uint2*)(ab + kc * 32);
                uint2 A1 = *(const uint2*)(ab + 8 * 160 + kc * 32);
#pragma unroll
                for (int nf = 0; nf < 12; nf++) {
                    int nfg = nh * 12 + nf;
                    uint2 Bv = *(const uint2*)((const char*)Bw +
                                ((kc * 24 + nfg) * 64 + g * 8 + tig * 2) * 4);
                    mma_fp16(acc[nf], A0.x, A1.x, A0.y, A1.y, Bv.x, Bv.y);
                }
            }

#pragma unroll
            for (int nf = 0; nf < 12; nf++) {
                float2 bb;
                if (nh == 0) bb = (nf < 8) ? *(const float2*)(bq + nf * 8 + tig * 2)
                                           : *(const float2*)(bv + (nf - 8) * 8 + tig * 2);
                else         bb = (nf < 8) ? *(const float2*)(bk + nf * 8 + tig * 2)
                                           : *(const float2*)(bv + 32 + (nf - 8) * 8 + tig * 2);
                acc[nf][0] += bb.x; acc[nf][1] += bb.y;
                acc[nf][2] += bb.x; acc[nf][3] += bb.y;
            }

            float ss0 = 0.f, ss1 = 0.f;
#pragma unroll
            for (int nf = 0; nf < 8; nf++) {
                ss0 += acc[nf][0] * acc[nf][0] + acc[nf][1] * acc[nf][1];
                ss1 += acc[nf][2] * acc[nf][2] + acc[nf][3] * acc[nf][3];
            }
            ss0 += __shfl_xor_sync(0xffffffffu, ss0, 1);
            ss0 += __shfl_xor_sync(0xffffffffu, ss0, 2);
            ss1 += __shfl_xor_sync(0xffffffffu, ss1, 1);
            ss1 += __shfl_xor_sync(0xffffffffu, ss1, 2);
            float inv0 = rsqrtf(ss0), inv1 = rsqrtf(ss1);
            const int pxA = px0 + mf * 16 + g, pxB = pxA + 8;

            if (nh == 0) {
#pragma unroll
                for (int nf = 0; nf < 8; nf++) {
                    int w = (nf >> 1) * 8 + tig * 2 + (nf & 1);
                    qn[pxA * 33 + w] = h2pack(acc[nf][0] * inv0, acc[nf][1] * inv0);
                    qn[pxB * 33 + w] = h2pack(acc[nf][2] * inv1, acc[nf][3] * inv1);
                }
            } else {
#pragma unroll
                for (int nf = 0; nf < 8; nf++) {
                    int m = nf * 8 + tig * 2;
                    knh[m * 136 + pxA]       = __float2half(acc[nf][0] * inv0);
                    knh[(m + 1) * 136 + pxA] = __float2half(acc[nf][1] * inv0);
                    knh[m * 136 + pxB]       = __float2half(acc[nf][2] * inv1);
                    knh[(m + 1) * 136 + pxB] = __float2half(acc[nf][3] * inv1);
                }
            }
#pragma unroll
            for (int nf = 8; nf < 12; nf++) {
                int cc = (nh ? 32 : 0) + (nf - 8) * 8 + tig * 2;
                vh[cc * 136 + pxA]       = __float2half(acc[nf][0]);
                vh[(cc + 1) * 136 + pxA] = __float2half(acc[nf][1]);
                vh[cc * 136 + pxB]       = __float2half(acc[nf][2]);
                vh[(cc + 1) * 136 + pxB] = __float2half(acc[nf][3]);
            }
        }
        __syncthreads();

        {
            uint32_t* gq = g_QnP + (((size_t)b << 16) + n0) * 32;
            for (int j = tid; j < 4096; j += 256)
                gq[j] = qn[(j >> 5) * 33 + (j & 31)];
        }

        if (tid < 128) {
            const uint32_t* rw = (tid < 64)
                ? (const uint32_t*)(sm + QK_KN) + tid * 68
                : (const uint32_t*)(sm + QK_V) + (tid - 64) * 68;
#pragma unroll 8
            for (int j = 0; j < 64; j++) { float2 f = h2up(rw[j]); ksacc += f.x + f.y; }
        }

        {
            const uint32_t* knw = (const uint32_t*)(sm + QK_KN);
            const uint32_t* vw  = (const uint32_t*)(sm + QK_V);
#pragma unroll
            for (int kc = 0; kc < 8; kc++) {
                int ra = (mt * 16 + g) * 68 + kc * 8 + tig;
                uint32_t a0 = knw[ra],          a2 = knw[ra + 4];
                uint32_t a1 = knw[ra + 8 * 68], a3 = knw[ra + 8 * 68 + 4];
#pragma unroll
                for (int nf = 0; nf < 4; nf++) {
                    int rb = (nh2 * 32 + nf * 8 + g) * 68 + kc * 8 + tig;
                    mma_fp16(ag[nf], a0, a1, a2, a3, vw[rb], vw[rb + 4]);
                }
            }
        }
        __syncthreads();
    }

    if (tid < 128) {
        float* dp = (tid < 64) ? &g_ksum[b * 64 + tid] : &g_vsum[b * 64 + tid - 64];
        atomicAdd(dp, ksacc);
    }

    {
        float* agg_s = (float*)(sm + QK_XA);
#pragma unroll
        for (int nf = 0; nf < 4; nf++) {
            int r0 = (mt * 16 + g) * 66 + nh2 * 32 + nf * 8 + tig * 2;
            *(float2*)&agg_s[r0]          = make_float2(ag[nf][0], ag[nf][1]);
            *(float2*)&agg_s[r0 + 8 * 66] = make_float2(ag[nf][2], ag[nf][3]);
        }
        __syncthreads();
        float* gp = gpart + (size_t)blockIdx.x * 4096;
        for (int j = tid; j < 4096; j += 256)
            gp[j] = agg_s[(j >> 6) * 66 + (j & 63)];
    }
}

// ---------------------------------------------------------------------------
__global__ void __launch_bounds__(256, 1)
k_red(const float* __restrict__ gpart) {
    int e = blockIdx.x * 256 + threadIdx.x;
    int b = e >> 12, idx = e & 4095;
    const float* p = gpart + ((size_t)b * 128) * 4096 + idx;
    float s0 = 0.f, s1 = 0.f, s2 = 0.f, s3 = 0.f;
#pragma unroll 4
    for (int q = 0; q < 128; q += 4) {
        s0 += p[(size_t)q * 4096];
        s1 += p[(size_t)(q + 1) * 4096];
        s2 += p[(size_t)(q + 2) * 4096];
        s3 += p[(size_t)(q + 3) * 4096];
    }
    g_aggkv[e] = (s0 + s1) + (s2 + s3);
}

// ---------------------------------------------------------------------------
__global__ void __launch_bounds__(256, 1)
k_fin(const float* __restrict__ Wr) {
    __shared__ float a_s[1024];
    __shared__ float w_s[4096];
    __shared__ float vs_s[64];

    int b  = blockIdx.x >> 2;
    int mq = blockIdx.x & 3;
    int tid = threadIdx.x;

    for (int idx = tid; idx < 4096; idx += 256) {
        int o = idx & 63, c = idx >> 6;
        w_s[c * 64 + o] = Wr[o * 64 + c];
    }
    for (int idx = tid; idx < 1024; idx += 256)
        a_s[idx] = g_aggkv[b * 4096 + mq * 1024 + idx];
    if (tid < 64) vs_s[tid] = g_vsum[b * 64 + tid];
    __syncthreads();

    int o = tid & 63, sub = tid >> 6;
    if (mq == 0 && sub == 0) {
        float s = 0.f;
#pragma unroll 8
        for (int c = 0; c < 64; c++) s += w_s[c * 64 + o] * vs_s[c];
        g_wrvs[b * 64 + o] = s;
    }
    int nf = o >> 3, gg = o & 7;
#pragma unroll
    for (int ml = sub * 4; ml < sub * 4 + 4; ml += 2) {
        int m = mq * 16 + ml;
        float t0 = 0.f, t1 = 0.f;
#pragma unroll 8
        for (int c = 0; c < 64; c++) {
            t0 += w_s[c * 64 + o] * a_s[ml * 64 + c];
            t1 += w_s[c * 64 + o] * a_s[(ml + 1) * 64 + c];
        }
        int kc = m >> 4, r = m & 15;
        int s2 = r >> 3, tg = (r & 7) >> 1;
        g_M2h[b * 2048 + ((kc * 8 + nf) * 64 + gg * 8 + tg * 2 + s2)] = h2pack(t0, t1);
    }
}

// ---------------------------------------------------------------------------
// k_attn: 1024 blocks; each handles 4 chunks of 128 px; M2/ks/wv/br staged once.
#define AT_QN   0
#define AT_M2   20480
#define AT_KS   28672
#define AT_WV   28928
#define AT_BR   29184
#define AT_SMEM 29440

__global__ void __launch_bounds__(256, 3)
k_attn(const float* __restrict__ br) {
    extern __shared__ char sm[];
    uint32_t* m2  = (uint32_t*)(sm + AT_M2);
    float*    ks  = (float*)(sm + AT_KS);
    float*    wv  = (float*)(sm + AT_WV);
    float*    brs = (float*)(sm + AT_BR);

    const int tid = threadIdx.x;
    const int b   = blockIdx.x >> 7;
    const int seg = blockIdx.x & 127;

    for (int i = tid; i < 2048; i += 256) m2[i] = g_M2h[b * 2048 + i];
    if (tid < 64) {
        ks[tid]  = g_ksum[b * 64 + tid] + 1e-6f;
        wv[tid]  = g_wrvs[b * 64 + tid];
        brs[tid] = __ldg(&br[tid]);
    }

    const int wid = tid >> 5, lane = tid & 31;
    const int g = lane >> 2, tig = lane & 3;
    const int px0 = wid << 4;

#pragma unroll 1
    for (int c = 0; c < 4; c++) {
        const int n0 = ((seg << 2) + c) << 7;

        {
            const uint4* gq = (const uint4*)(g_QnP + (((size_t)b << 16) + n0) * 32);
            for (int i = tid; i < 1024; i += 256) {
                int px = i >> 3, q4 = i & 7;
                *(uint4*)(sm + (px * 40 + q4 * 4) * 4) = __ldg(gq + px * 8 + q4);
            }
        }
        __syncthreads();

        float acc[8][4];
#pragma unroll
        for (int nf = 0; nf < 8; nf++)
#pragma unroll
            for (int r = 0; r < 4; r++) acc[nf][r] = 0.f;
        float dot0 = 0.f, dot1 = 0.f;

#pragma unroll
        for (int kc = 0; kc < 4; kc++) {
            const char* ab = sm + ((px0 + g) * 40 + tig * 2) * 4;
            uint2 A0 = *(const uint2*)(ab + kc * 32);
            uint2 A1 = *(const uint2*)(ab + 8 * 160 + kc * 32);
            float2 ka = *(const float2*)&ks[kc * 16 + tig * 2];
            float2 kb = *(const float2*)&ks[kc * 16 + tig * 2 + 8];
            float2 f;
            f = h2up(A0.x); dot0 += f.x * ka.x + f.y * ka.y;
            f = h2up(A0.y); dot0 += f.x * kb.x + f.y * kb.y;
            f = h2up(A1.x); dot1 += f.x * ka.x + f.y * ka.y;
            f = h2up(A1.y); dot1 += f.x * kb.x + f.y * kb.y;
#pragma unroll
            for (int nf = 0; nf < 8; nf++) {
                uint2 Bv = *(const uint2*)((const char*)m2 +
                            ((kc * 8 + nf) * 64 + g * 8 + tig * 2) * 4);
                mma_fp16(acc[nf], A0.x, A1.x, A0.y, A1.y, Bv.x, Bv.y);
            }
        }
        dot0 += __shfl_xor_sync(0xffffffffu, dot0, 1);
        dot0 += __shfl_xor_sync(0xffffffffu, dot0, 2);
        dot1 += __shfl_xor_sync(0xffffffffu, dot1, 1);
        dot1 += __shfl_xor_sync(0xffffffffu, dot1, 2);
        float den0 = 1.f / (65536.f + dot0);
        float den1 = 1.f / (65536.f + dot1);

        uint32_t* ga = g_attnP + (((size_t)b << 16) + n0) * 32;
#pragma unroll
        for (int nf = 0; nf < 8; nf++) {
            int o = nf * 8 + tig * 2;
            int w = (nf >> 1) * 8 + tig * 2 + (nf & 1);
            float v0 = brs[o]     + den0 * (wv[o]     + acc[nf][0]);
            float v1 = brs[o + 1] + den0 * (wv[o + 1] + acc[nf][1]);
            float v2 = brs[o]     + den1 * (wv[o]     + acc[nf][2]);
            float v3 = brs[o + 1] + den1 * (wv[o + 1] + acc[nf][3]);
            ga[(px0 + g) * 32 + w]     = h2pack(v0, v1);
            ga[(px0 + g + 8) * 32 + w] = h2pack(v2, v3);
        }
        __syncthreads();   // Qn reads done before next chunk overwrites
    }
}

// ---------------------------------------------------------------------------
// conv3x3 via mma.sync fp16, occ 2, cp.async staging overlapped with epilogue.
// B fragments loaded via paired-nf LDS.128 (R14-verified layout).
#define CB_OFF   256
#define CA_OFF   37120
#define CA_SLOT  10560
#define CV_SMEM  100480

__device__ __forceinline__ void cv_stage_row_async(uint32_t sbase, int slot,
                                                   const uint4* __restrict__ src,
                                                   int b, int gy, int x0, int tid) {
    uint32_t d0 = sbase + CA_OFF + slot * CA_SLOT;
    bool rowok = ((unsigned)gy < 256u);
    const uint4* sp = src + (((size_t)(b * 65536 + (rowok ? gy : 0) * 256)) << 3);
    for (int i = tid; i < 528; i += 256) {
        int px = i >> 3, q4 = i & 7;
        int gx = x0 - 1 + px;
        bool ok = rowok && ((unsigned)gx < 256u);
        cp16(d0 + (uint32_t)((px * 40 + q4 * 4) * 4),
             sp + (((ok ? gx : 0)) << 3) + q4, ok ? 16 : 0);
    }
}

__global__ void __launch_bounds__(256, 2)
k_conv_mma(const uint4* __restrict__ srcP, const float* __restrict__ bias,
           float* __restrict__ dstF, uint32_t* __restrict__ dstP,
           const float* __restrict__ xres, int fuse, int convIdx) {
    extern __shared__ char smc[];
    const uint32_t sbase = smem_u32(smc);
    const int tid = threadIdx.x;
    const int wid = tid >> 5;
    const int lane = tid & 31;
    const int g   = lane >> 2;
    const int tig = lane & 3;

    const int nh   = blockIdx.x & 1;
    const int xq   = (blockIdx.x >> 1) & 3;
    const int band = (blockIdx.x >> 3) & 31;
    const int b    = blockIdx.x >> 8;
    const int y0   = band << 3;
    const int x0   = xq << 6;

    if (tid < 64) ((float*)smc)[tid] = bias[tid];
    {
        // paired-nf layout: smem [chunk 36][nfp 2][lane 32] uint4
        const uint4* bsrc = (const uint4*)(g_convB + convIdx * 18432);
        uint4* bdst = (uint4*)(smc + CB_OFF);
        for (int q = tid; q < 2304; q += 256) {
            int c = q >> 6, nfp = (q >> 5) & 1, ln = q & 31;
            bdst[q] = bsrc[c * 128 + (nh * 2 + nfp) * 32 + ln];
        }
    }

    cv_stage_row_async(sbase, (y0)     % 6, srcP, b, y0 - 1, x0, tid);
    cv_stage_row_async(sbase, (y0 + 1) % 6, srcP, b, y0,     x0, tid);
    cv_stage_row_async(sbase, (y0 + 2) % 6, srcP, b, y0 + 1, x0, tid);
    cv_stage_row_async(sbase, (y0 + 3) % 6, srcP, b, y0 + 2, x0, tid);
    cv_stage_row_async(sbase, (y0 + 4) % 6, srcP, b, y0 + 3, x0, tid);
    cv_stage_row_async(sbase, (y0 + 5) % 6, srcP, b, y0 + 4, x0, tid);
    CP_COMMIT();
    CP_WAIT0();
    __syncthreads();

    const int rsel = wid >> 1;
    const int px0  = (wid & 1) << 5;

    for (int t = 0; t < 8; t += 4) {
        const int y = y0 + t + rsel;

        float acc[2][4][4];
#pragma unroll
        for (int mf = 0; mf < 2; mf++)
#pragma unroll
            for (int nf = 0; nf < 4; nf++)
#pragma unroll
                for (int r = 0; r < 4; r++) acc[mf][nf][r] = 0.f;

#pragma unroll
        for (int ky = 0; ky < 3; ky++) {
            const char* aSlot = smc + CA_OFF + ((y + ky) % 6) * CA_SLOT;
#pragma unroll
            for (int kx = 0; kx < 3; kx++) {
                const char* aBase0 = aSlot + ((px0 + kx + g) * 40 + tig * 2) * 4;
                const char* aBase1 = aSlot + ((px0 + 16 + kx + g) * 40 + tig * 2) * 4;
                const int tap = ky * 3 + kx;
#pragma unroll
                for (int kc = 0; kc < 4; kc++) {
                    uint2 A0 = *(const uint2*)(aBase0 + kc * 32);
                    uint2 A1 = *(const uint2*)(aBase0 + 8 * 160 + kc * 32);
                    uint2 A2 = *(const uint2*)(aBase1 + kc * 32);
                    uint2 A3 = *(const uint2*)(aBase1 + 8 * 160 + kc * 32);
                    const uint4* bq = (const uint4*)(smc + CB_OFF)
                                      + ((tap * 4 + kc) * 2) * 32 + lane;
                    uint4 B0 = bq[0];
                    uint4 B1 = bq[32];
                    mma_fp16(acc[0][0], A0.x, A1.x, A0.y, A1.y, B0.x, B0.y);
                    mma_fp16(acc[0][1], A0.x, A1.x, A0.y, A1.y, B0.z, B0.w);
                    mma_fp16(acc[0][2], A0.x, A1.x, A0.y, A1.y, B1.x, B1.y);
                    mma_fp16(acc[0][3], A0.x, A1.x, A0.y, A1.y, B1.z, B1.w);
                    mma_fp16(acc[1][0], A2.x, A3.x, A2.y, A3.y, B0.x, B0.y);
                    mma_fp16(acc[1][1], A2.x, A3.x, A2.y, A3.y, B0.z, B0.w);
                    mma_fp16(acc[1][2], A2.x, A3.x, A2.y, A3.y, B1.x, B1.y);
                    mma_fp16(acc[1][3], A2.x, A3.x, A2.y, A3.y, B1.z, B1.w);
                }
            }
        }

        if (t == 0) {
            __syncthreads();
            cv_stage_row_async(sbase, (y0 + 6) % 6, srcP, b, y0 + 5, x0, tid);
            cv_stage_row_async(sbase, (y0 + 7) % 6, srcP, b, y0 + 6, x0, tid);
            cv_stage_row_async(sbase, (y0 + 8) % 6, srcP, b, y0 + 7, x0, tid);
            cv_stage_row_async(sbase, (y0 + 9) % 6, srcP, b, y0 + 8, x0, tid);
            CP_COMMIT();
        }

        {
            const float* bs = (const float*)smc;
#pragma unroll
            for (int mf = 0; mf < 2; mf++) {
                const int pxA = x0 + px0 + mf * 16 + g;
                const int pxB = pxA + 8;
                if (fuse) {
                    const size_t rowOff = ((size_t)b << 22) + ((size_t)y << 8);
#pragma unroll
                    for (int nf = 0; nf < 4; nf++) {
                        int o0 = nh * 32 + nf * 8 + tig * 2;
                        float b0v = bs[o0], b1v = bs[o0 + 1];
                        size_t i00 = rowOff + ((size_t)o0 << 16) + pxA;
                        size_t i01 = rowOff + ((size_t)(o0 + 1) << 16) + pxA;
                        size_t i10 = rowOff + ((size_t)o0 << 16) + pxB;
                        size_t i11 = rowOff + ((size_t)(o0 + 1) << 16) + pxB;
                        float v00 = acc[mf][nf][0] + b0v;
                        float v01 = acc[mf][nf][1] + b1v;
                        float v10 = acc[mf][nf][2] + b0v;
                        float v11 = acc[mf][nf][3] + b1v;
                        float xa = xres[i00], xb2 = xres[i01];
                        float xc = xres[i10], xd = xres[i11];
                        dstF[i00] = v00 * xa + xa;
                        dstF[i01] = v01 * xb2 + xb2;
                        dstF[i10] = v10 * xc + xc;
                        dstF[i11] = v11 * xd + xd;
                    }
                } else {
                    const size_t rowBase = ((size_t)(b * 65536 + y * 256));
#pragma unroll
                    for (int nf = 0; nf < 4; nf++) {
                        int nfg = nh * 4 + nf;
                        int o0 = nfg * 8 + tig * 2;
                        float b0v = bs[o0], b1v = bs[o0 + 1];
                        int w = (nfg >> 1) * 8 + tig * 2 + (nfg & 1);
                        size_t baseA = (rowBase + pxA) * 32 + w;
                        size_t baseB = (rowBase + pxB) * 32 + w;
                        dstP[baseA] = h2pack(acc[mf][nf][0] + b0v, acc[mf][nf][1] + b1v);
                        dstP[baseB] = h2pack(acc[mf][nf][2] + b0v, acc[mf][nf][3] + b1v);
                    }
                }
            }
        }

        if (t == 0) {
            CP_WAIT0();
            __syncthreads();
        }
    }
}

// ---------------------------------------------------------------------------
extern "C" void kernel_launch(void* const* d_in, const int* in_sizes, int n_in,
                              void* d_out, int out_size) {
    const float* x  = (const float*)d_in[0];
    const float* Wq = (const float*)d_in[1];
    const float* bq = (const float*)d_in[2];
    const float* Wk = (const float*)d_in[3];
    const float* bk = (const float*)d_in[4];
    const float* Wv = (const float*)d_in[5];
    const float* bv = (const float*)d_in[6];
    const float* Wr = (const float*)d_in[7];
    const float* br = (const float*)d_in[8];
    const float* W1 = (const float*)d_in[9];
    const float* b1 = (const float*)d_in[10];
    const float* W2 = (const float*)d_in[11];
    const float* b2 = (const float*)d_in[12];
    float* out = (float*)d_out;

    cudaFuncSetAttribute(k_qkv,      cudaFuncAttributeMaxDynamicSharedMemorySize, QK_SMEM);
    cudaFuncSetAttribute(k_attn,     cudaFuncAttributeMaxDynamicSharedMemorySize, AT_SMEM);
    cudaFuncSetAttribute(k_conv_mma, cudaFuncAttributeMaxDynamicSharedMemorySize, CV_SMEM);

    void *p_attnP, *p_t1P;
    cudaGetSymbolAddress(&p_attnP, g_attnP);
    cudaGetSymbolAddress(&p_t1P, g_t1P);

    k_prep<<<144, 256>>>(Wq, Wk, Wv, W1, W2, 0);
    k_prep<<<24, 256>>>(Wq, Wk, Wv, W1, W2, 1);
    k_prep<<<2, 256>>>(Wq, Wk, Wv, W1, W2, 2);
    k_qkv<<<1024, 256, QK_SMEM>>>(x, bq, bk, bv, (float*)p_t1P);   // profile slot 3
    k_red<<<128, 256>>>((const float*)p_t1P);
    k_fin<<<32, 256>>>(Wr);
    k_attn<<<1024, 256, AT_SMEM>>>(br);
    k_conv_mma<<<2048, 256, CV_SMEM>>>((const uint4*)p_attnP, b1, nullptr,
                                       (uint32_t*)p_t1P, nullptr, 0, 0);
    k_conv_mma<<<2048, 256, CV_SMEM>>>((const uint4*)p_t1P, b2, out,
                                       nullptr, x, 1, 1);
}